// round 6
// baseline (speedup 1.0000x reference)
#include <cuda_runtime.h>
#include <cuda_bf16.h>
#include <math.h>
#include <stdint.h>

// Problem constants
constexpr int T   = 2048;
constexpr int D   = 2048;
constexpr int DC  = 512;
constexpr int NH  = 16;
constexpr int DH  = 128;
constexpr int DRH = 64;
constexpr int QKD = DH + DRH; // 192

typedef __nv_bfloat16 bf16;

// ------------------------------------------------------------------
// Scratch (device globals — no allocation allowed)
// All GEMM operands live as split bf16 pairs (hi, lo); hi+lo = 4B/elem.
// ------------------------------------------------------------------
__device__ bf16 g_hh[T * D],  g_hl[T * D];            // h split
__device__ bf16 g_wdkvh[DC * D], g_wdkvl[DC * D];
__device__ bf16 g_wdqh [DC * D], g_wdql [DC * D];
__device__ bf16 g_wkrh [DRH * D], g_wkrl [DRH * D];

__device__ bf16 g_Bukh[NH * DH * DC], g_Bukl[NH * DH * DC];
__device__ bf16 g_Buvh[NH * DH * DC], g_Buvl[NH * DH * DC];
__device__ bf16 g_Buqh[NH * DH * DC], g_Buql[NH * DH * DC];
__device__ bf16 g_Bqrh[NH * DRH * DC], g_Bqrl[NH * DRH * DC];
__device__ bf16 g_Wth [D * NH * DH],  g_Wtl [D * NH * DH];

__device__ bf16 g_ckvh[T * DC], g_ckvl[T * DC];
__device__ bf16 g_cqh [T * DC], g_cql [T * DC];
__device__ float g_kr [T * DRH];

__device__ float g_KC[T * NH * DH];
__device__ float g_VC[T * NH * DH];
__device__ float g_QC[T * NH * DH];
__device__ float g_QR[T * NH * DRH];

__device__ bf16 g_qh[(size_t)NH * T * QKD], g_ql[(size_t)NH * T * QKD];
__device__ bf16 g_kh[(size_t)NH * T * QKD], g_kl[(size_t)NH * T * QKD];
__device__ float g_v[(size_t)NH * T * DH];
__device__ bf16 g_vth[(size_t)NH * DH * T], g_vtl[(size_t)NH * DH * T];

__device__ float g_S[(size_t)NH * T * T];                       // logits/probs fp32
__device__ bf16 g_Sth[(size_t)NH * T * T], g_Stl[(size_t)NH * T * T];  // probs^T split
__device__ bf16 g_Uh[(size_t)T * NH * DH], g_Ul[(size_t)T * NH * DH];

// ------------------------------------------------------------------
// Helpers
// ------------------------------------------------------------------
__device__ __forceinline__ void cp_async16(void* smem_dst, const void* gsrc)
{
    unsigned s = (unsigned)__cvta_generic_to_shared(smem_dst);
    asm volatile("cp.async.cg.shared.global [%0], [%1], 16;" :: "r"(s), "l"(gsrc));
}
__device__ __forceinline__ void cp_commit() { asm volatile("cp.async.commit_group;"); }
template <int NG> __device__ __forceinline__ void cp_wait() { asm volatile("cp.async.wait_group %0;" :: "n"(NG)); }

__device__ __forceinline__ void splitf(float v, bf16& h, bf16& l)
{
    h = __float2bfloat16_rn(v);
    l = __float2bfloat16_rn(v - __bfloat162float(h));
}

#define MMA_BF16(d, a0, a1, a2, a3, b0, b1)                                   \
    asm volatile(                                                             \
        "mma.sync.aligned.m16n8k16.row.col.f32.bf16.bf16.f32 "                \
        "{%0,%1,%2,%3}, {%4,%5,%6,%7}, {%8,%9}, {%0,%1,%2,%3};"               \
        : "+f"(d[0]), "+f"(d[1]), "+f"(d[2]), "+f"(d[3])                      \
        : "r"(a0), "r"(a1), "r"(a2), "r"(a3), "r"(b0), "r"(b1))

// ------------------------------------------------------------------
// bf16x3 tensor-core GEMM, NT, pre-split operands, cp.async 2-stage.
//   A(h/l): M x K (lda), B(h/l): N x K (ldb), both bf16 row-major.
//   Output: fp32 (Cf) and/or split bf16 (Ch, Cl); null disables.
//   M % 128 == 0, K % 32 == 0, N >= 64 (B rows clamped, stores guarded).
//   causal: skip tiles bn_blk > bm_blk.  kdiag: K-loop starts at bm.
// ------------------------------------------------------------------
constexpr int BM = 128, BN = 128, BK = 32;
constexpr int SWU = 20;                  // uints per smem row (16 data + 4 pad)
constexpr int STAGE_U = BM * SWU;        // uints per array per stage
constexpr int SMEM_BYTES = 4 * 2 * STAGE_U * 4;   // 4 arrays, 2 stages = 81920 B

__global__ __launch_bounds__(256, 2)
void bgemm_bf16x3(const bf16* __restrict__ Ah, const bf16* __restrict__ Al,
                  const bf16* __restrict__ Bh, const bf16* __restrict__ Bl,
                  float* Cf, bf16* Ch, bf16* Cl,
                  int M, int N, int K, int lda, int ldb, int ldc, float alpha,
                  long long sA, long long sB, long long sC, int causal, int kdiag)
{
    const int bmb = blockIdx.x, bnb = blockIdx.y;
    if (causal && bnb > bmb) return;
    const int bm = bmb * BM, bn = bnb * BN;
    Ah += (long long)blockIdx.z * sA;  Al += (long long)blockIdx.z * sA;
    Bh += (long long)blockIdx.z * sB;  Bl += (long long)blockIdx.z * sB;
    const long long co = (long long)blockIdx.z * sC;

    extern __shared__ unsigned smem[];

    const int tid = threadIdx.x;
    const int lane = tid & 31, warp = tid >> 5;
    const int g = lane >> 2, tig = lane & 3;
    const int wm = (warp & 3) * 32;
    const int wn = (warp >> 2) * 64;

    auto buf = [&](int st, int a) -> unsigned* { return smem + (st * 4 + a) * STAGE_U; };

    auto load_stage = [&](int st, int k0) {
        unsigned *pAh = buf(st, 0), *pAl = buf(st, 1), *pBh = buf(st, 2), *pBl = buf(st, 3);
#pragma unroll
        for (int i = 0; i < 2; i++) {
            int idx = tid + i * 256;            // 0..511
            int row = idx >> 2;                 // 0..127
            int seg = idx & 3;                  // 16B segment (8 bf16)
            size_t ao = (size_t)(bm + row) * lda + k0 + seg * 8;
            cp_async16(pAh + row * SWU + seg * 4, Ah + ao);
            cp_async16(pAl + row * SWU + seg * 4, Al + ao);
            int rn = bn + row; if (rn > N - 1) rn = N - 1;
            size_t bo = (size_t)rn * ldb + k0 + seg * 8;
            cp_async16(pBh + row * SWU + seg * 4, Bh + bo);
            cp_async16(pBl + row * SWU + seg * 4, Bl + bo);
        }
    };

    float acc[2][8][4] = {};

    int k0 = kdiag ? bm : 0;
    int stage = 0;
    load_stage(0, k0);
    cp_commit();

    for (; k0 < K; k0 += BK) {
        if (k0 + BK < K) {
            load_stage(stage ^ 1, k0 + BK);
            cp_commit();
            cp_wait<1>();
        } else {
            cp_wait<0>();
        }
        __syncthreads();

        const unsigned *pAh = buf(stage, 0), *pAl = buf(stage, 1);
        const unsigned *pBh = buf(stage, 2), *pBl = buf(stage, 3);

#pragma unroll
        for (int ks = 0; ks < 2; ks++) {
            const int kp = ks * 8 + tig;
            unsigned ah[2][4], al[2][4];
#pragma unroll
            for (int mt = 0; mt < 2; mt++) {
                int r0 = wm + mt * 16 + g;
                ah[mt][0] = pAh[r0 * SWU + kp];           ah[mt][1] = pAh[(r0 + 8) * SWU + kp];
                ah[mt][2] = pAh[r0 * SWU + kp + 4];       ah[mt][3] = pAh[(r0 + 8) * SWU + kp + 4];
                al[mt][0] = pAl[r0 * SWU + kp];           al[mt][1] = pAl[(r0 + 8) * SWU + kp];
                al[mt][2] = pAl[r0 * SWU + kp + 4];       al[mt][3] = pAl[(r0 + 8) * SWU + kp + 4];
            }
#pragma unroll
            for (int nt = 0; nt < 8; nt++) {
                int c0 = wn + nt * 8 + g;
                unsigned bh0 = pBh[c0 * SWU + kp], bh1 = pBh[c0 * SWU + kp + 4];
                unsigned bl0 = pBl[c0 * SWU + kp], bl1 = pBl[c0 * SWU + kp + 4];
#pragma unroll
                for (int mt = 0; mt < 2; mt++) {
                    MMA_BF16(acc[mt][nt], ah[mt][0], ah[mt][1], ah[mt][2], ah[mt][3], bh0, bh1);
                    MMA_BF16(acc[mt][nt], al[mt][0], al[mt][1], al[mt][2], al[mt][3], bh0, bh1);
                    MMA_BF16(acc[mt][nt], ah[mt][0], ah[mt][1], ah[mt][2], ah[mt][3], bl0, bl1);
                }
            }
        }
        __syncthreads();
        stage ^= 1;
    }

    // Epilogue: fp32 and/or split bf16
#pragma unroll
    for (int mt = 0; mt < 2; mt++) {
        int row = bm + wm + mt * 16 + g;
#pragma unroll
        for (int nt = 0; nt < 8; nt++) {
            int col = bn + wn + nt * 8 + 2 * tig;
            if (col >= N) continue;
            size_t o0 = co + (size_t)row * ldc + col;
            size_t o1 = co + (size_t)(row + 8) * ldc + col;
            float v0 = alpha * acc[mt][nt][0], v1 = alpha * acc[mt][nt][1];
            float v2 = alpha * acc[mt][nt][2], v3 = alpha * acc[mt][nt][3];
            if (Cf) {
                *(float2*)(Cf + o0) = make_float2(v0, v1);
                *(float2*)(Cf + o1) = make_float2(v2, v3);
            }
            if (Ch) {
                bf16 h0, l0, h1, l1;
                splitf(v0, h0, l0); splitf(v1, h1, l1);
                *(__nv_bfloat162*)(Ch + o0) = __nv_bfloat162(h0, h1);
                *(__nv_bfloat162*)(Cl + o0) = __nv_bfloat162(l0, l1);
                splitf(v2, h0, l0); splitf(v3, h1, l1);
                *(__nv_bfloat162*)(Ch + o1) = __nv_bfloat162(h0, h1);
                *(__nv_bfloat162*)(Cl + o1) = __nv_bfloat162(l0, l1);
            }
        }
    }
}

// ------------------------------------------------------------------
// Elementwise split: fp32 -> (hi, lo)
// ------------------------------------------------------------------
__global__ void splitk(const float* __restrict__ in, bf16* __restrict__ hi,
                       bf16* __restrict__ lo, int n)
{
    int i = blockIdx.x * blockDim.x + threadIdx.x;
    if (i >= n) return;
    bf16 h, l;
    splitf(in[i], h, l);
    hi[i] = h; lo[i] = l;
}

// w: [E, NH, DC] -> out(h/l): [(n*E+e), c]
__global__ void repack_up_split(const float* __restrict__ w, bf16* __restrict__ oh,
                                bf16* __restrict__ ol, int E)
{
    int idx = blockIdx.x * blockDim.x + threadIdx.x;
    int total = E * NH * DC;
    if (idx >= total) return;
    int c = idx % DC;
    int rest = idx / DC;
    int n = rest % NH;
    int e = rest / NH;
    bf16 h, l;
    splitf(w[idx], h, l);
    size_t o = (size_t)(n * E + e) * DC + c;
    oh[o] = h; ol[o] = l;
}

// w_o: [D, DH, NH] -> Wt(h/l): [d, n*DH+e]
__global__ void repack_wo_split(const float* __restrict__ w)
{
    int idx = blockIdx.x * blockDim.x + threadIdx.x;
    int total = D * DH * NH;
    if (idx >= total) return;
    int n = idx % NH;
    int rest = idx / NH;
    int e = rest % DH;
    int d = rest / DH;
    bf16 h, l;
    splitf(w[idx], h, l);
    size_t o = (size_t)d * (NH * DH) + n * DH + e;
    g_Wth[o] = h; g_Wtl[o] = l;
}

// ------------------------------------------------------------------
// Assemble Q, K (split bf16) + V (fp32) per head + RoPE.  grid (T,NH), block 192
// ------------------------------------------------------------------
__global__ void assemble(const float* __restrict__ freqs)
{
    int t = blockIdx.x;
    int n = blockIdx.y;
    int i = threadIdx.x;
    size_t qo = ((size_t)n * T + t) * QKD + i;

    float qv, kv;
    if (i < DH) {
        qv = g_QC[(size_t)t * (NH * DH) + n * DH + i];
        kv = g_KC[(size_t)t * (NH * DH) + n * DH + i];
        g_v[((size_t)n * T + t) * DH + i] = g_VC[(size_t)t * (NH * DH) + n * DH + i];
    } else {
        int j = i - DH;
        int jr = j & 31;
        float ang = freqs[t * (DRH / 2) + jr];
        float cs, sn;
        sincosf(ang, &sn, &cs);
        float qre = g_QR[(size_t)t * (NH * DRH) + n * DRH + jr];
        float qim = g_QR[(size_t)t * (NH * DRH) + n * DRH + 32 + jr];
        float kre = g_kr[(size_t)t * DRH + jr];
        float kim = g_kr[(size_t)t * DRH + 32 + jr];
        if (j < 32) { qv = qre * cs - qim * sn; kv = (kre * cs - kim * sn) * (1.0f / NH); }
        else        { qv = qre * sn + qim * cs; kv = (kre * sn + kim * cs) * (1.0f / NH); }
    }
    bf16 h, l;
    splitf(qv, h, l); g_qh[qo] = h; g_ql[qo] = l;
    splitf(kv, h, l); g_kh[qo] = h; g_kl[qo] = l;
}

// ------------------------------------------------------------------
// Causal row softmax, in place on g_S. grid (T, NH), block 256.
// ------------------------------------------------------------------
__global__ void softmax_causal()
{
    int t = blockIdx.x;
    int n = blockIdx.y;
    float* row = g_S + ((size_t)n * T + t) * T;

    __shared__ float buf[T];
    __shared__ float red[256];
    int tid = threadIdx.x;
    int L = t + 1;

    float mx = -3.0e38f;
    for (int l = tid; l < L; l += 256) {
        float v = row[l];
        buf[l] = v;
        mx = fmaxf(mx, v);
    }
    red[tid] = mx;
    __syncthreads();
    for (int s = 128; s > 0; s >>= 1) {
        if (tid < s) red[tid] = fmaxf(red[tid], red[tid + s]);
        __syncthreads();
    }
    mx = red[0];
    __syncthreads();

    float sum = 0.0f;
    for (int l = tid; l < L; l += 256) {
        float e = __expf(buf[l] - mx);
        buf[l] = e;
        sum += e;
    }
    red[tid] = sum;
    __syncthreads();
    for (int s = 128; s > 0; s >>= 1) {
        if (tid < s) red[tid] += red[tid + s];
        __syncthreads();
    }
    float inv = 1.0f / red[0];
    for (int l = tid; l < T; l += 256) row[l] = (l < L) ? buf[l] * inv : 0.0f;
}

// ------------------------------------------------------------------
// 32x32 tiled transpose fp32 -> split bf16: out[c][r] = split(in[r][c]).
// block (32,8). grid (Cin/32, Rin/32, Z).
// tri=1: skip out-tiles never read by the diagonal-start PV GEMM.
// ------------------------------------------------------------------
__global__ void transpose32_split(const float* __restrict__ in,
                                  bf16* __restrict__ oh, bf16* __restrict__ ol,
                                  int Rin, int Cin, long long sIn, long long sOut, int tri)
{
    int cb = blockIdx.x;
    int rb = blockIdx.y;
    if (tri && rb < (cb & ~3)) return;
    const float* pin = in + (long long)blockIdx.z * sIn;
    bf16* ph = oh + (long long)blockIdx.z * sOut;
    bf16* pl = ol + (long long)blockIdx.z * sOut;

    __shared__ float tile[32][33];
    int tx = threadIdx.x, ty = threadIdx.y;
#pragma unroll
    for (int i = 0; i < 4; i++) {
        int r = rb * 32 + ty + i * 8;
        tile[ty + i * 8][tx] = pin[(size_t)r * Cin + cb * 32 + tx];
    }
    __syncthreads();
#pragma unroll
    for (int i = 0; i < 4; i++) {
        int c = cb * 32 + ty + i * 8;
        bf16 h, l;
        splitf(tile[tx][ty + i * 8], h, l);
        size_t o = (size_t)c * Rin + rb * 32 + tx;
        ph[o] = h; pl[o] = l;
    }
}

// ------------------------------------------------------------------
// Launch
// ------------------------------------------------------------------
static void* sym_addr(const void* symbol)
{
    void* p = nullptr;
    cudaGetSymbolAddress(&p, symbol);
    return p;
}

extern "C" void kernel_launch(void* const* d_in, const int* in_sizes, int n_in,
                              void* d_out, int out_size)
{
    const float* h     = (const float*)d_in[0];
    const float* freqs = (const float*)d_in[1];
    // d_in[2] = mask (unused: causal handled analytically)
    const float* w_dkv = (const float*)d_in[3];
    const float* w_uk  = (const float*)d_in[4];
    const float* w_uv  = (const float*)d_in[5];
    const float* w_dq  = (const float*)d_in[6];
    const float* w_uq  = (const float*)d_in[7];
    const float* w_qr  = (const float*)d_in[8];
    const float* w_kr  = (const float*)d_in[9];
    const float* w_o   = (const float*)d_in[10];
    float* out = (float*)d_out;

    cudaFuncSetAttribute(bgemm_bf16x3, cudaFuncAttributeMaxDynamicSharedMemorySize, SMEM_BYTES);

    bf16 *p_hh = (bf16*)sym_addr(g_hh), *p_hl = (bf16*)sym_addr(g_hl);
    bf16 *p_wdkvh = (bf16*)sym_addr(g_wdkvh), *p_wdkvl = (bf16*)sym_addr(g_wdkvl);
    bf16 *p_wdqh = (bf16*)sym_addr(g_wdqh), *p_wdql = (bf16*)sym_addr(g_wdql);
    bf16 *p_wkrh = (bf16*)sym_addr(g_wkrh), *p_wkrl = (bf16*)sym_addr(g_wkrl);
    bf16 *p_Bukh = (bf16*)sym_addr(g_Bukh), *p_Bukl = (bf16*)sym_addr(g_Bukl);
    bf16 *p_Buvh = (bf16*)sym_addr(g_Buvh), *p_Buvl = (bf16*)sym_addr(g_Buvl);
    bf16 *p_Buqh = (bf16*)sym_addr(g_Buqh), *p_Buql = (bf16*)sym_addr(g_Buql);
    bf16 *p_Bqrh = (bf16*)sym_addr(g_Bqrh), *p_Bqrl = (bf16*)sym_addr(g_Bqrl);
    bf16 *p_Wth = (bf16*)sym_addr(g_Wth), *p_Wtl = (bf16*)sym_addr(g_Wtl);
    bf16 *p_ckvh = (bf16*)sym_addr(g_ckvh), *p_ckvl = (bf16*)sym_addr(g_ckvl);
    bf16 *p_cqh = (bf16*)sym_addr(g_cqh), *p_cql = (bf16*)sym_addr(g_cql);
    float *p_kr = (float*)sym_addr(g_kr);
    float *p_KC = (float*)sym_addr(g_KC), *p_VC = (float*)sym_addr(g_VC);
    float *p_QC = (float*)sym_addr(g_QC), *p_QR = (float*)sym_addr(g_QR);
    bf16 *p_qh = (bf16*)sym_addr(g_qh), *p_ql = (bf16*)sym_addr(g_ql);
    bf16 *p_kh = (bf16*)sym_addr(g_kh), *p_kl = (bf16*)sym_addr(g_kl);
    float *p_v = (float*)sym_addr(g_v);
    bf16 *p_vth = (bf16*)sym_addr(g_vth), *p_vtl = (bf16*)sym_addr(g_vtl);
    float *p_S = (float*)sym_addr(g_S);
    bf16 *p_Sth = (bf16*)sym_addr(g_Sth), *p_Stl = (bf16*)sym_addr(g_Stl);
    bf16 *p_Uh = (bf16*)sym_addr(g_Uh), *p_Ul = (bf16*)sym_addr(g_Ul);

    const float scale = 1.0f / sqrtf((float)QKD);
    const int smem = SMEM_BYTES;

    // 1) split inputs / repack weights into bf16 hi/lo
    splitk<<<(T * D + 255) / 256, 256>>>(h, p_hh, p_hl, T * D);
    splitk<<<(DC * D + 255) / 256, 256>>>(w_dkv, p_wdkvh, p_wdkvl, DC * D);
    splitk<<<(DC * D + 255) / 256, 256>>>(w_dq, p_wdqh, p_wdql, DC * D);
    splitk<<<(DRH * D + 255) / 256, 256>>>(w_kr, p_wkrh, p_wkrl, DRH * D);
    {
        int tot = DH * NH * DC;
        repack_up_split<<<(tot + 255) / 256, 256>>>(w_uk, p_Bukh, p_Bukl, DH);
        repack_up_split<<<(tot + 255) / 256, 256>>>(w_uv, p_Buvh, p_Buvl, DH);
        repack_up_split<<<(tot + 255) / 256, 256>>>(w_uq, p_Buqh, p_Buql, DH);
        int tot2 = DRH * NH * DC;
        repack_up_split<<<(tot2 + 255) / 256, 256>>>(w_qr, p_Bqrh, p_Bqrl, DRH);
        int tot3 = D * DH * NH;
        repack_wo_split<<<(tot3 + 255) / 256, 256>>>(w_o);
    }

    // 2) down projections (split outputs) + k_r (fp32 output)
    bgemm_bf16x3<<<dim3(T / BM, DC / BN, 1), 256, smem>>>(p_hh, p_hl, p_wdkvh, p_wdkvl,
        nullptr, p_ckvh, p_ckvl, T, DC, D, D, D, DC, 1.0f, 0, 0, 0, 0, 0);
    bgemm_bf16x3<<<dim3(T / BM, DC / BN, 1), 256, smem>>>(p_hh, p_hl, p_wdqh, p_wdql,
        nullptr, p_cqh, p_cql, T, DC, D, D, D, DC, 1.0f, 0, 0, 0, 0, 0);
    bgemm_bf16x3<<<dim3(T / BM, 1, 1), 256, smem>>>(p_hh, p_hl, p_wkrh, p_wkrl,
        p_kr, nullptr, nullptr, T, DRH, D, D, D, DRH, 1.0f, 0, 0, 0, 0, 0);

    // 3) up projections (fp32 outputs -> assemble)
    bgemm_bf16x3<<<dim3(T / BM, (NH * DH) / BN, 1), 256, smem>>>(p_ckvh, p_ckvl, p_Bukh, p_Bukl,
        p_KC, nullptr, nullptr, T, NH * DH, DC, DC, DC, NH * DH, 1.0f, 0, 0, 0, 0, 0);
    bgemm_bf16x3<<<dim3(T / BM, (NH * DH) / BN, 1), 256, smem>>>(p_ckvh, p_ckvl, p_Buvh, p_Buvl,
        p_VC, nullptr, nullptr, T, NH * DH, DC, DC, DC, NH * DH, 1.0f, 0, 0, 0, 0, 0);
    bgemm_bf16x3<<<dim3(T / BM, (NH * DH) / BN, 1), 256, smem>>>(p_cqh, p_cql, p_Buqh, p_Buql,
        p_QC, nullptr, nullptr, T, NH * DH, DC, DC, DC, NH * DH, 1.0f, 0, 0, 0, 0, 0);
    bgemm_bf16x3<<<dim3(T / BM, (NH * DRH) / BN, 1), 256, smem>>>(p_cqh, p_cql, p_Bqrh, p_Bqrl,
        p_QR, nullptr, nullptr, T, NH * DRH, DC, DC, DC, NH * DRH, 1.0f, 0, 0, 0, 0, 0);

    // 4) assemble q/k (split) + v (fp32) with RoPE
    assemble<<<dim3(T, NH), QKD>>>(freqs);

    // 5) logits: S = scale * q @ k^T, causal tiles only, fp32 out
    bgemm_bf16x3<<<dim3(T / BM, T / BN, NH), 256, smem>>>(p_qh, p_ql, p_kh, p_kl,
        p_S, nullptr, nullptr, T, T, QKD, QKD, QKD, T, scale,
        (long long)T * QKD, (long long)T * QKD, (long long)T * T, 1, 0);

    // 6) causal softmax (exact zeros above diagonal)
    softmax_causal<<<dim3(T, NH), 256>>>();

    // 7) transposes -> split bf16: S -> St(h/l) (pruned), v -> vt(h/l)
    transpose32_split<<<dim3(T / 32, T / 32, NH), dim3(32, 8)>>>(p_S, p_Sth, p_Stl, T, T,
        (long long)T * T, (long long)T * T, 1);
    transpose32_split<<<dim3(DH / 32, T / 32, NH), dim3(32, 8)>>>(p_v, p_vth, p_vtl, T, DH,
        (long long)T * DH, (long long)DH * T, 0);

    // 8) U = P^T @ V (split out), K-loop from diagonal
    bgemm_bf16x3<<<dim3(T / BM, 1, NH), 256, smem>>>(p_Sth, p_Stl, p_vth, p_vtl,
        nullptr, p_Uh, p_Ul, T, DH, T, T, T, NH * DH, 1.0f,
        (long long)T * T, (long long)DH * T, (long long)DH, 0, 1);

    // 9) final: out = U @ Wt^T (fp32)
    bgemm_bf16x3<<<dim3(T / BM, D / BN, 1), 256, smem>>>(p_Uh, p_Ul, p_Wth, p_Wtl,
        out, nullptr, nullptr, T, D, NH * DH, NH * DH, D, D, 1.0f, 0, 0, 0, 0, 0);
}

// round 9
// speedup vs baseline: 1.2868x; 1.2868x over previous
#include <cuda_runtime.h>
#include <cuda_bf16.h>
#include <math.h>
#include <stdint.h>

// Problem constants
constexpr int T   = 2048;
constexpr int D   = 2048;
constexpr int DC  = 512;
constexpr int NH  = 16;
constexpr int DH  = 128;
constexpr int DRH = 64;
constexpr int QKD = DH + DRH; // 192

typedef __nv_bfloat16 bf16;

// ------------------------------------------------------------------
// Scratch (device globals — no allocation allowed)
// All GEMM operands are split bf16 pairs (hi, lo). 16B-aligned.
// ------------------------------------------------------------------
__device__ __align__(128) bf16 g_hh[T * D];
__device__ __align__(128) bf16 g_hl[T * D];
__device__ __align__(128) bf16 g_wdkvh[DC * D];
__device__ __align__(128) bf16 g_wdkvl[DC * D];
__device__ __align__(128) bf16 g_wdqh [DC * D];
__device__ __align__(128) bf16 g_wdql [DC * D];
__device__ __align__(128) bf16 g_wkrh [DRH * D];
__device__ __align__(128) bf16 g_wkrl [DRH * D];

__device__ __align__(128) bf16 g_Bukh[NH * DH * DC];
__device__ __align__(128) bf16 g_Bukl[NH * DH * DC];
__device__ __align__(128) bf16 g_Buvh[NH * DH * DC];
__device__ __align__(128) bf16 g_Buvl[NH * DH * DC];
__device__ __align__(128) bf16 g_Buqh[NH * DH * DC];
__device__ __align__(128) bf16 g_Buql[NH * DH * DC];
__device__ __align__(128) bf16 g_Bqrh[NH * DRH * DC];
__device__ __align__(128) bf16 g_Bqrl[NH * DRH * DC];
__device__ __align__(128) bf16 g_Wth [D * NH * DH];
__device__ __align__(128) bf16 g_Wtl [D * NH * DH];

__device__ __align__(128) bf16 g_ckvh[T * DC];
__device__ __align__(128) bf16 g_ckvl[T * DC];
__device__ __align__(128) bf16 g_cqh [T * DC];
__device__ __align__(128) bf16 g_cql [T * DC];
__device__ float g_kr [T * DRH];

__device__ float g_KC[T * NH * DH];
__device__ float g_VC[T * NH * DH];
__device__ float g_QC[T * NH * DH];
__device__ float g_QR[T * NH * DRH];

__device__ __align__(128) bf16 g_qh[(size_t)NH * T * QKD];
__device__ __align__(128) bf16 g_ql[(size_t)NH * T * QKD];
__device__ __align__(128) bf16 g_kh[(size_t)NH * T * QKD];
__device__ __align__(128) bf16 g_kl[(size_t)NH * T * QKD];
__device__ float g_v[(size_t)NH * T * DH];
__device__ __align__(128) bf16 g_vth[(size_t)NH * DH * T];
__device__ __align__(128) bf16 g_vtl[(size_t)NH * DH * T];

__device__ float g_S[(size_t)NH * T * T];                       // logits/probs fp32
__device__ __align__(128) bf16 g_Sth[(size_t)NH * T * T];
__device__ __align__(128) bf16 g_Stl[(size_t)NH * T * T];
__device__ __align__(128) bf16 g_Uh[(size_t)T * NH * DH];
__device__ __align__(128) bf16 g_Ul[(size_t)T * NH * DH];

// ------------------------------------------------------------------
// Helpers
// ------------------------------------------------------------------
__device__ __forceinline__ void splitf(float v, bf16& h, bf16& l)
{
    h = __float2bfloat16_rn(v);
    l = __float2bfloat16_rn(v - __bfloat162float(h));
}

#define MMA_BF16(d, a0, a1, a2, a3, b0, b1)                                   \
    asm volatile(                                                             \
        "mma.sync.aligned.m16n8k16.row.col.f32.bf16.bf16.f32 "                \
        "{%0,%1,%2,%3}, {%4,%5,%6,%7}, {%8,%9}, {%0,%1,%2,%3};"               \
        : "+f"(d[0]), "+f"(d[1]), "+f"(d[2]), "+f"(d[3])                      \
        : "r"(a0), "r"(a1), "r"(a2), "r"(a3), "r"(b0), "r"(b1))

// ------------------------------------------------------------------
// bf16x3 tensor-core GEMM, NT: C = alpha * (A_h+A_l) @ (B_h+B_l)^T (AlBl dropped)
//   A(h/l): M x K (lda), B(h/l): N x K (ldb), bf16 row-major, pre-split.
//   Output: fp32 (Cf) and/or split bf16 (Ch, Cl); null disables.
//   M % 128 == 0, K % 32 == 0, N >= 64 (B rows clamped, stores guarded).
//   causal: skip tiles bn_blk > bm_blk.  kdiag: K-loop starts at bm.
//   Structure identical to the proven R2 kernel; only the load phase
//   changed (direct uint2 loads of pre-split bf16, no conversion).
// ------------------------------------------------------------------
constexpr int BM = 128, BN = 128, BK = 32;
constexpr int SW = BK / 2 + 4;   // 20 words: stride ≡ 20 mod 32 -> conflict-free frags

__global__ __launch_bounds__(256, 2)
void bgemm_nt(const bf16* __restrict__ Ah, const bf16* __restrict__ Al,
              const bf16* __restrict__ Bh, const bf16* __restrict__ Bl,
              float* Cf, bf16* Ch, bf16* Cl,
              int M, int N, int K, int lda, int ldb, int ldc, float alpha,
              long long sA, long long sB, long long sC, int causal, int kdiag)
{
    const int bmb = blockIdx.x, bnb = blockIdx.y;
    if (causal && bnb > bmb) return;
    const int bm = bmb * BM, bn = bnb * BN;
    Ah += (long long)blockIdx.z * sA;  Al += (long long)blockIdx.z * sA;
    Bh += (long long)blockIdx.z * sB;  Bl += (long long)blockIdx.z * sB;
    const long long co = (long long)blockIdx.z * sC;

    __shared__ unsigned sAh[BM][SW], sAl[BM][SW];
    __shared__ unsigned sBh[BN][SW], sBl[BN][SW];

    const int tid = threadIdx.x;
    const int lane = tid & 31, warp = tid >> 5;
    const int g = lane >> 2, tig = lane & 3;
    const int wm = (warp & 3) * 32;    // warp M offset
    const int wn = (warp >> 2) * 64;   // warp N offset

    float acc[2][8][4] = {};

    int k0 = kdiag ? bm : 0;

    for (; k0 < K; k0 += BK) {
#pragma unroll
        for (int i = 0; i < 4; i++) {
            int idx = tid + i * 256;      // 0..1023 over 128x8 (r, kq) pairs
            int r  = idx >> 3;            // 0..127
            int kq = idx & 7;             // k = kq*4 (4 bf16 = 8 bytes)
            size_t ao = (size_t)(bm + r) * lda + (k0 + kq * 4);
            uint2 avh = *(const uint2*)(Ah + ao);
            uint2 avl = *(const uint2*)(Al + ao);
            sAh[r][kq * 2] = avh.x; sAh[r][kq * 2 + 1] = avh.y;
            sAl[r][kq * 2] = avl.x; sAl[r][kq * 2 + 1] = avl.y;

            int rn = bn + r; if (rn > N - 1) rn = N - 1;
            size_t bo = (size_t)rn * ldb + (k0 + kq * 4);
            uint2 bvh = *(const uint2*)(Bh + bo);
            uint2 bvl = *(const uint2*)(Bl + bo);
            sBh[r][kq * 2] = bvh.x; sBh[r][kq * 2 + 1] = bvh.y;
            sBl[r][kq * 2] = bvl.x; sBl[r][kq * 2 + 1] = bvl.y;
        }
        __syncthreads();

#pragma unroll
        for (int ks = 0; ks < 2; ks++) {
            const int kp = ks * 8 + tig;
            unsigned ah[2][4], al[2][4];
#pragma unroll
            for (int mt = 0; mt < 2; mt++) {
                int r0 = wm + mt * 16 + g;
                ah[mt][0] = sAh[r0][kp];     ah[mt][1] = sAh[r0 + 8][kp];
                ah[mt][2] = sAh[r0][kp + 4]; ah[mt][3] = sAh[r0 + 8][kp + 4];
                al[mt][0] = sAl[r0][kp];     al[mt][1] = sAl[r0 + 8][kp];
                al[mt][2] = sAl[r0][kp + 4]; al[mt][3] = sAl[r0 + 8][kp + 4];
            }
#pragma unroll
            for (int nt = 0; nt < 8; nt++) {
                int c0 = wn + nt * 8 + g;
                unsigned bh0 = sBh[c0][kp], bh1 = sBh[c0][kp + 4];
                unsigned bl0 = sBl[c0][kp], bl1 = sBl[c0][kp + 4];
#pragma unroll
                for (int mt = 0; mt < 2; mt++) {
                    MMA_BF16(acc[mt][nt], ah[mt][0], ah[mt][1], ah[mt][2], ah[mt][3], bh0, bh1);
                    MMA_BF16(acc[mt][nt], al[mt][0], al[mt][1], al[mt][2], al[mt][3], bh0, bh1);
                    MMA_BF16(acc[mt][nt], ah[mt][0], ah[mt][1], ah[mt][2], ah[mt][3], bl0, bl1);
                }
            }
        }
        __syncthreads();
    }

    // Epilogue: fp32 and/or split bf16
#pragma unroll
    for (int mt = 0; mt < 2; mt++) {
        int row = bm + wm + mt * 16 + g;
#pragma unroll
        for (int nt = 0; nt < 8; nt++) {
            int col = bn + wn + nt * 8 + 2 * tig;
            if (col >= N) continue;
            size_t o0 = co + (size_t)row * ldc + col;
            size_t o1 = co + (size_t)(row + 8) * ldc + col;
            float v0 = alpha * acc[mt][nt][0], v1 = alpha * acc[mt][nt][1];
            float v2 = alpha * acc[mt][nt][2], v3 = alpha * acc[mt][nt][3];
            if (Cf) {
                *(float2*)(Cf + o0) = make_float2(v0, v1);
                *(float2*)(Cf + o1) = make_float2(v2, v3);
            }
            if (Ch) {
                bf16 h0, l0, h1, l1;
                splitf(v0, h0, l0); splitf(v1, h1, l1);
                *(__nv_bfloat162*)(Ch + o0) = __nv_bfloat162(h0, h1);
                *(__nv_bfloat162*)(Cl + o0) = __nv_bfloat162(l0, l1);
                splitf(v2, h0, l0); splitf(v3, h1, l1);
                *(__nv_bfloat162*)(Ch + o1) = __nv_bfloat162(h0, h1);
                *(__nv_bfloat162*)(Cl + o1) = __nv_bfloat162(l0, l1);
            }
        }
    }
}

// ------------------------------------------------------------------
// Elementwise split: fp32 -> (hi, lo)
// ------------------------------------------------------------------
__global__ void splitk(const float* __restrict__ in, bf16* __restrict__ hi,
                       bf16* __restrict__ lo, int n)
{
    int i = blockIdx.x * blockDim.x + threadIdx.x;
    if (i >= n) return;
    bf16 h, l;
    splitf(in[i], h, l);
    hi[i] = h; lo[i] = l;
}

// w: [E, NH, DC] -> out(h/l): [(n*E+e), c]
__global__ void repack_up_split(const float* __restrict__ w, bf16* __restrict__ oh,
                                bf16* __restrict__ ol, int E)
{
    int idx = blockIdx.x * blockDim.x + threadIdx.x;
    int total = E * NH * DC;
    if (idx >= total) return;
    int c = idx % DC;
    int rest = idx / DC;
    int n = rest % NH;
    int e = rest / NH;
    bf16 h, l;
    splitf(w[idx], h, l);
    size_t o = (size_t)(n * E + e) * DC + c;
    oh[o] = h; ol[o] = l;
}

// w_o: [D, DH, NH] -> Wt(h/l): [d, n*DH+e]
__global__ void repack_wo_split(const float* __restrict__ w)
{
    int idx = blockIdx.x * blockDim.x + threadIdx.x;
    int total = D * DH * NH;
    if (idx >= total) return;
    int n = idx % NH;
    int rest = idx / NH;
    int e = rest % DH;
    int d = rest / DH;
    bf16 h, l;
    splitf(w[idx], h, l);
    size_t o = (size_t)d * (NH * DH) + n * DH + e;
    g_Wth[o] = h; g_Wtl[o] = l;
}

// ------------------------------------------------------------------
// Assemble Q, K (split bf16) + V (fp32) per head + RoPE.  grid (T,NH), block 192
// ------------------------------------------------------------------
__global__ void assemble(const float* __restrict__ freqs)
{
    int t = blockIdx.x;
    int n = blockIdx.y;
    int i = threadIdx.x;
    size_t qo = ((size_t)n * T + t) * QKD + i;

    float qv, kv;
    if (i < DH) {
        qv = g_QC[(size_t)t * (NH * DH) + n * DH + i];
        kv = g_KC[(size_t)t * (NH * DH) + n * DH + i];
        g_v[((size_t)n * T + t) * DH + i] = g_VC[(size_t)t * (NH * DH) + n * DH + i];
    } else {
        int j = i - DH;
        int jr = j & 31;
        float ang = freqs[t * (DRH / 2) + jr];
        float cs, sn;
        sincosf(ang, &sn, &cs);
        float qre = g_QR[(size_t)t * (NH * DRH) + n * DRH + jr];
        float qim = g_QR[(size_t)t * (NH * DRH) + n * DRH + 32 + jr];
        float kre = g_kr[(size_t)t * DRH + jr];
        float kim = g_kr[(size_t)t * DRH + 32 + jr];
        if (j < 32) { qv = qre * cs - qim * sn; kv = (kre * cs - kim * sn) * (1.0f / NH); }
        else        { qv = qre * sn + qim * cs; kv = (kre * sn + kim * cs) * (1.0f / NH); }
    }
    bf16 h, l;
    splitf(qv, h, l); g_qh[qo] = h; g_ql[qo] = l;
    splitf(kv, h, l); g_kh[qo] = h; g_kl[qo] = l;
}

// ------------------------------------------------------------------
// Causal row softmax, in place on g_S. grid (T, NH), block 256.
// ------------------------------------------------------------------
__global__ void softmax_causal()
{
    int t = blockIdx.x;
    int n = blockIdx.y;
    float* row = g_S + ((size_t)n * T + t) * T;

    __shared__ float buf[T];
    __shared__ float red[256];
    int tid = threadIdx.x;
    int L = t + 1;

    float mx = -3.0e38f;
    for (int l = tid; l < L; l += 256) {
        float v = row[l];
        buf[l] = v;
        mx = fmaxf(mx, v);
    }
    red[tid] = mx;
    __syncthreads();
    for (int s = 128; s > 0; s >>= 1) {
        if (tid < s) red[tid] = fmaxf(red[tid], red[tid + s]);
        __syncthreads();
    }
    mx = red[0];
    __syncthreads();

    float sum = 0.0f;
    for (int l = tid; l < L; l += 256) {
        float e = __expf(buf[l] - mx);
        buf[l] = e;
        sum += e;
    }
    red[tid] = sum;
    __syncthreads();
    for (int s = 128; s > 0; s >>= 1) {
        if (tid < s) red[tid] += red[tid + s];
        __syncthreads();
    }
    float inv = 1.0f / red[0];
    for (int l = tid; l < T; l += 256) row[l] = (l < L) ? buf[l] * inv : 0.0f;
}

// ------------------------------------------------------------------
// 32x32 tiled transpose fp32 -> split bf16: out[c][r] = split(in[r][c]).
// block (32,8). grid (Cin/32, Rin/32, Z).
// tri=1: skip out-tiles never read by the diagonal-start PV GEMM.
// ------------------------------------------------------------------
__global__ void transpose32_split(const float* __restrict__ in,
                                  bf16* __restrict__ oh, bf16* __restrict__ ol,
                                  int Rin, int Cin, long long sIn, long long sOut, int tri)
{
    int cb = blockIdx.x;
    int rb = blockIdx.y;
    if (tri && rb < (cb & ~3)) return;
    const float* pin = in + (long long)blockIdx.z * sIn;
    bf16* phh = oh + (long long)blockIdx.z * sOut;
    bf16* pll = ol + (long long)blockIdx.z * sOut;

    __shared__ float tile[32][33];
    int tx = threadIdx.x, ty = threadIdx.y;
#pragma unroll
    for (int i = 0; i < 4; i++) {
        int r = rb * 32 + ty + i * 8;
        tile[ty + i * 8][tx] = pin[(size_t)r * Cin + cb * 32 + tx];
    }
    __syncthreads();
#pragma unroll
    for (int i = 0; i < 4; i++) {
        int c = cb * 32 + ty + i * 8;
        bf16 h, l;
        splitf(tile[tx][ty + i * 8], h, l);
        size_t o = (size_t)c * Rin + rb * 32 + tx;
        phh[o] = h; pll[o] = l;
    }
}

// ------------------------------------------------------------------
// Launch
// ------------------------------------------------------------------
static void* sym_addr(const void* symbol)
{
    void* p = nullptr;
    cudaGetSymbolAddress(&p, symbol);
    return p;
}

extern "C" void kernel_launch(void* const* d_in, const int* in_sizes, int n_in,
                              void* d_out, int out_size)
{
    const float* h     = (const float*)d_in[0];
    const float* freqs = (const float*)d_in[1];
    // d_in[2] = mask (unused: causal handled analytically)
    const float* w_dkv = (const float*)d_in[3];
    const float* w_uk  = (const float*)d_in[4];
    const float* w_uv  = (const float*)d_in[5];
    const float* w_dq  = (const float*)d_in[6];
    const float* w_uq  = (const float*)d_in[7];
    const float* w_qr  = (const float*)d_in[8];
    const float* w_kr  = (const float*)d_in[9];
    const float* w_o   = (const float*)d_in[10];
    float* out = (float*)d_out;

    bf16 *p_hh = (bf16*)sym_addr(g_hh), *p_hl = (bf16*)sym_addr(g_hl);
    bf16 *p_wdkvh = (bf16*)sym_addr(g_wdkvh), *p_wdkvl = (bf16*)sym_addr(g_wdkvl);
    bf16 *p_wdqh = (bf16*)sym_addr(g_wdqh), *p_wdql = (bf16*)sym_addr(g_wdql);
    bf16 *p_wkrh = (bf16*)sym_addr(g_wkrh), *p_wkrl = (bf16*)sym_addr(g_wkrl);
    bf16 *p_Bukh = (bf16*)sym_addr(g_Bukh), *p_Bukl = (bf16*)sym_addr(g_Bukl);
    bf16 *p_Buvh = (bf16*)sym_addr(g_Buvh), *p_Buvl = (bf16*)sym_addr(g_Buvl);
    bf16 *p_Buqh = (bf16*)sym_addr(g_Buqh), *p_Buql = (bf16*)sym_addr(g_Buql);
    bf16 *p_Bqrh = (bf16*)sym_addr(g_Bqrh), *p_Bqrl = (bf16*)sym_addr(g_Bqrl);
    bf16 *p_Wth = (bf16*)sym_addr(g_Wth), *p_Wtl = (bf16*)sym_addr(g_Wtl);
    bf16 *p_ckvh = (bf16*)sym_addr(g_ckvh), *p_ckvl = (bf16*)sym_addr(g_ckvl);
    bf16 *p_cqh = (bf16*)sym_addr(g_cqh), *p_cql = (bf16*)sym_addr(g_cql);
    float *p_kr = (float*)sym_addr(g_kr);
    float *p_KC = (float*)sym_addr(g_KC), *p_VC = (float*)sym_addr(g_VC);
    float *p_QC = (float*)sym_addr(g_QC), *p_QR = (float*)sym_addr(g_QR);
    bf16 *p_qh = (bf16*)sym_addr(g_qh), *p_ql = (bf16*)sym_addr(g_ql);
    bf16 *p_kh = (bf16*)sym_addr(g_kh), *p_kl = (bf16*)sym_addr(g_kl);
    float *p_v = (float*)sym_addr(g_v);
    bf16 *p_vth = (bf16*)sym_addr(g_vth), *p_vtl = (bf16*)sym_addr(g_vtl);
    float *p_S = (float*)sym_addr(g_S);
    bf16 *p_Sth = (bf16*)sym_addr(g_Sth), *p_Stl = (bf16*)sym_addr(g_Stl);
    bf16 *p_Uh = (bf16*)sym_addr(g_Uh), *p_Ul = (bf16*)sym_addr(g_Ul);

    const float scale = 1.0f / sqrtf((float)QKD);

    // 1) split inputs / repack weights into bf16 hi/lo
    splitk<<<(T * D + 255) / 256, 256>>>(h, p_hh, p_hl, T * D);
    splitk<<<(DC * D + 255) / 256, 256>>>(w_dkv, p_wdkvh, p_wdkvl, DC * D);
    splitk<<<(DC * D + 255) / 256, 256>>>(w_dq, p_wdqh, p_wdql, DC * D);
    splitk<<<(DRH * D + 255) / 256, 256>>>(w_kr, p_wkrh, p_wkrl, DRH * D);
    {
        int tot = DH * NH * DC;
        repack_up_split<<<(tot + 255) / 256, 256>>>(w_uk, p_Bukh, p_Bukl, DH);
        repack_up_split<<<(tot + 255) / 256, 256>>>(w_uv, p_Buvh, p_Buvl, DH);
        repack_up_split<<<(tot + 255) / 256, 256>>>(w_uq, p_Buqh, p_Buql, DH);
        int tot2 = DRH * NH * DC;
        repack_up_split<<<(tot2 + 255) / 256, 256>>>(w_qr, p_Bqrh, p_Bqrl, DRH);
        int tot3 = D * DH * NH;
        repack_wo_split<<<(tot3 + 255) / 256, 256>>>(w_o);
    }

    // 2) down projections (split outputs) + k_r (fp32 output)
    bgemm_nt<<<dim3(T / BM, DC / BN, 1), 256>>>(p_hh, p_hl, p_wdkvh, p_wdkvl,
        nullptr, p_ckvh, p_ckvl, T, DC, D, D, D, DC, 1.0f, 0, 0, 0, 0, 0);
    bgemm_nt<<<dim3(T / BM, DC / BN, 1), 256>>>(p_hh, p_hl, p_wdqh, p_wdql,
        nullptr, p_cqh, p_cql, T, DC, D, D, D, DC, 1.0f, 0, 0, 0, 0, 0);
    bgemm_nt<<<dim3(T / BM, 1, 1), 256>>>(p_hh, p_hl, p_wkrh, p_wkrl,
        p_kr, nullptr, nullptr, T, DRH, D, D, D, DRH, 1.0f, 0, 0, 0, 0, 0);

    // 3) up projections (fp32 outputs -> assemble)
    bgemm_nt<<<dim3(T / BM, (NH * DH) / BN, 1), 256>>>(p_ckvh, p_ckvl, p_Bukh, p_Bukl,
        p_KC, nullptr, nullptr, T, NH * DH, DC, DC, DC, NH * DH, 1.0f, 0, 0, 0, 0, 0);
    bgemm_nt<<<dim3(T / BM, (NH * DH) / BN, 1), 256>>>(p_ckvh, p_ckvl, p_Buvh, p_Buvl,
        p_VC, nullptr, nullptr, T, NH * DH, DC, DC, DC, NH * DH, 1.0f, 0, 0, 0, 0, 0);
    bgemm_nt<<<dim3(T / BM, (NH * DH) / BN, 1), 256>>>(p_cqh, p_cql, p_Buqh, p_Buql,
        p_QC, nullptr, nullptr, T, NH * DH, DC, DC, DC, NH * DH, 1.0f, 0, 0, 0, 0, 0);
    bgemm_nt<<<dim3(T / BM, (NH * DRH) / BN, 1), 256>>>(p_cqh, p_cql, p_Bqrh, p_Bqrl,
        p_QR, nullptr, nullptr, T, NH * DRH, DC, DC, DC, NH * DRH, 1.0f, 0, 0, 0, 0, 0);

    // 4) assemble q/k (split) + v (fp32) with RoPE
    assemble<<<dim3(T, NH), QKD>>>(freqs);

    // 5) logits: S = scale * q @ k^T, causal tiles only, fp32 out
    bgemm_nt<<<dim3(T / BM, T / BN, NH), 256>>>(p_qh, p_ql, p_kh, p_kl,
        p_S, nullptr, nullptr, T, T, QKD, QKD, QKD, T, scale,
        (long long)T * QKD, (long long)T * QKD, (long long)T * T, 1, 0);

    // 6) causal softmax (exact zeros above diagonal)
    softmax_causal<<<dim3(T, NH), 256>>>();

    // 7) transposes -> split bf16: S -> St(h/l) (pruned), v -> vt(h/l)
    transpose32_split<<<dim3(T / 32, T / 32, NH), dim3(32, 8)>>>(p_S, p_Sth, p_Stl, T, T,
        (long long)T * T, (long long)T * T, 1);
    transpose32_split<<<dim3(DH / 32, T / 32, NH), dim3(32, 8)>>>(p_v, p_vth, p_vtl, T, DH,
        (long long)T * DH, (long long)DH * T, 0);

    // 8) U = P^T @ V (split out), K-loop from diagonal
    bgemm_nt<<<dim3(T / BM, 1, NH), 256>>>(p_Sth, p_Stl, p_vth, p_vtl,
        nullptr, p_Uh, p_Ul, T, DH, T, T, T, NH * DH, 1.0f,
        (long long)T * T, (long long)DH * T, (long long)DH, 0, 1);

    // 9) final: out = U @ Wt^T (fp32)
    bgemm_nt<<<dim3(T / BM, D / BN, 1), 256>>>(p_Uh, p_Ul, p_Wth, p_Wtl,
        out, nullptr, nullptr, T, D, NH * DH, NH * DH, D, D, 1.0f, 0, 0, 0, 0, 0);
}

// round 12
// speedup vs baseline: 1.3801x; 1.0726x over previous
#include <cuda_runtime.h>
#include <cuda_bf16.h>
#include <math.h>
#include <stdint.h>

// Problem constants
constexpr int T   = 2048;
constexpr int D   = 2048;
constexpr int DC  = 512;
constexpr int NH  = 16;
constexpr int DH  = 128;
constexpr int DRH = 64;
constexpr int QKD = DH + DRH; // 192

typedef __nv_bfloat16 bf16;

// ------------------------------------------------------------------
// Scratch (device globals — no allocation allowed)
// All GEMM operands are split bf16 pairs (hi, lo). 16B-aligned.
// ------------------------------------------------------------------
__device__ __align__(128) bf16 g_hh[T * D];
__device__ __align__(128) bf16 g_hl[T * D];
__device__ __align__(128) bf16 g_wdkvh[DC * D];
__device__ __align__(128) bf16 g_wdkvl[DC * D];
__device__ __align__(128) bf16 g_wdqh [DC * D];
__device__ __align__(128) bf16 g_wdql [DC * D];
__device__ __align__(128) bf16 g_wkrh [DRH * D];
__device__ __align__(128) bf16 g_wkrl [DRH * D];

__device__ __align__(128) bf16 g_Bukh[NH * DH * DC];
__device__ __align__(128) bf16 g_Bukl[NH * DH * DC];
__device__ __align__(128) bf16 g_Buvh[NH * DH * DC];
__device__ __align__(128) bf16 g_Buvl[NH * DH * DC];
__device__ __align__(128) bf16 g_Buqh[NH * DH * DC];
__device__ __align__(128) bf16 g_Buql[NH * DH * DC];
__device__ __align__(128) bf16 g_Bqrh[NH * DRH * DC];
__device__ __align__(128) bf16 g_Bqrl[NH * DRH * DC];
__device__ __align__(128) bf16 g_Wth [D * NH * DH];
__device__ __align__(128) bf16 g_Wtl [D * NH * DH];

__device__ __align__(128) bf16 g_ckvh[T * DC];
__device__ __align__(128) bf16 g_ckvl[T * DC];
__device__ __align__(128) bf16 g_cqh [T * DC];
__device__ __align__(128) bf16 g_cql [T * DC];
__device__ float g_kr [T * DRH];

__device__ float g_KC[T * NH * DH];
__device__ float g_VC[T * NH * DH];
__device__ float g_QC[T * NH * DH];
__device__ float g_QR[T * NH * DRH];

__device__ __align__(128) bf16 g_qh[(size_t)NH * T * QKD];
__device__ __align__(128) bf16 g_ql[(size_t)NH * T * QKD];
__device__ __align__(128) bf16 g_kh[(size_t)NH * T * QKD];
__device__ __align__(128) bf16 g_kl[(size_t)NH * T * QKD];
__device__ float g_v[(size_t)NH * T * DH];
__device__ __align__(128) bf16 g_vth[(size_t)NH * DH * T];
__device__ __align__(128) bf16 g_vtl[(size_t)NH * DH * T];

__device__ float g_S[(size_t)NH * T * T];                       // logits/probs fp32
__device__ __align__(128) bf16 g_Sth[(size_t)NH * T * T];
__device__ __align__(128) bf16 g_Stl[(size_t)NH * T * T];
__device__ __align__(128) bf16 g_Uh[(size_t)T * NH * DH];
__device__ __align__(128) bf16 g_Ul[(size_t)T * NH * DH];

// ------------------------------------------------------------------
// Helpers
// ------------------------------------------------------------------
__device__ __forceinline__ void splitf(float v, bf16& h, bf16& l)
{
    h = __float2bfloat16_rn(v);
    l = __float2bfloat16_rn(v - __bfloat162float(h));
}

// cp.async.ca: 16B, L1-allocating (adjacent CTAs share the B panel in L1)
__device__ __forceinline__ void cp_async16(void* sdst, const void* gsrc)
{
    unsigned s = (unsigned)__cvta_generic_to_shared(sdst);
    asm volatile("cp.async.ca.shared.global [%0], [%1], 16;" :: "r"(s), "l"(gsrc));
}
__device__ __forceinline__ void cp_commit() { asm volatile("cp.async.commit_group;"); }
template <int NG> __device__ __forceinline__ void cp_wait() { asm volatile("cp.async.wait_group %0;" :: "n"(NG)); }

#define MMA_BF16(d, a0, a1, a2, a3, b0, b1)                                   \
    asm volatile(                                                             \
        "mma.sync.aligned.m16n8k16.row.col.f32.bf16.bf16.f32 "                \
        "{%0,%1,%2,%3}, {%4,%5,%6,%7}, {%8,%9}, {%0,%1,%2,%3};"               \
        : "+f"(d[0]), "+f"(d[1]), "+f"(d[2]), "+f"(d[3])                      \
        : "r"(a0), "r"(a1), "r"(a2), "r"(a3), "r"(b0), "r"(b1))

// ------------------------------------------------------------------
// bf16x3 tensor-core GEMM, NT: C = alpha * (A_h+A_l) @ (B_h+B_l)^T (AlBl dropped)
//   A(h/l): M x K (lda), B(h/l): N x K (ldb), bf16 row-major, pre-split.
//   Output: fp32 (Cf) and/or split bf16 (Ch, Cl); null disables.
//   M % 128 == 0, K % 32 == 0, N >= 64 (B rows clamped, stores guarded).
//   causal: skip tiles bn_blk > bm_blk.  kdiag: K-loop starts at bm.
//   R8 structure + 2-stage cp.async.ca double buffer, one sync per k-tile.
// ------------------------------------------------------------------
constexpr int BM = 128, BN = 128, BK = 32;
constexpr int SWU = 20;                         // words per smem row (16 data + 4 pad)
constexpr int ARR_B = BM * SWU * 4;             // 10240 B per operand array
constexpr int DYN_SMEM = 2 * 4 * ARR_B;         // 2 stages x 4 arrays = 81920 B

__global__ __launch_bounds__(256, 2)
void bgemm_nt(const bf16* __restrict__ Ah, const bf16* __restrict__ Al,
              const bf16* __restrict__ Bh, const bf16* __restrict__ Bl,
              float* Cf, bf16* Ch, bf16* Cl,
              int M, int N, int K, int lda, int ldb, int ldc, float alpha,
              long long sA, long long sB, long long sC, int causal, int kdiag)
{
    const int bmb = blockIdx.x, bnb = blockIdx.y;
    if (causal && bnb > bmb) return;
    const int bm = bmb * BM, bn = bnb * BN;
    Ah += (long long)blockIdx.z * sA;  Al += (long long)blockIdx.z * sA;
    Bh += (long long)blockIdx.z * sB;  Bl += (long long)blockIdx.z * sB;
    const long long co = (long long)blockIdx.z * sC;

    extern __shared__ __align__(16) char dsm[];

    const int tid = threadIdx.x;
    const int lane = tid & 31, warp = tid >> 5;
    const int g = lane >> 2, tig = lane & 3;
    const int wm = (warp & 3) * 32;    // warp M offset
    const int wn = (warp >> 2) * 64;   // warp N offset

    // per-stage operand arrays
    unsigned* bufs[2][4];
#pragma unroll
    for (int s = 0; s < 2; s++)
#pragma unroll
        for (int a = 0; a < 4; a++)
            bufs[s][a] = (unsigned*)(dsm + (s * 4 + a) * ARR_B);

    // this thread's two (row, 16B-segment) load slots
    const int r0l = tid >> 2,        seg0 = tid & 3;          // chunks 0..255
    const int r1l = (tid + 256) >> 2, seg1 = (tid + 256) & 3; // chunks 256..511

    auto load_stage = [&](int st, int k0) {
        unsigned *pAh = bufs[st][0], *pAl = bufs[st][1];
        unsigned *pBh = bufs[st][2], *pBl = bufs[st][3];
        {
            size_t ao = (size_t)(bm + r0l) * lda + k0 + seg0 * 8;
            cp_async16(pAh + r0l * SWU + seg0 * 4, Ah + ao);
            cp_async16(pAl + r0l * SWU + seg0 * 4, Al + ao);
            int rn = bn + r0l; if (rn > N - 1) rn = N - 1;
            size_t bo = (size_t)rn * ldb + k0 + seg0 * 8;
            cp_async16(pBh + r0l * SWU + seg0 * 4, Bh + bo);
            cp_async16(pBl + r0l * SWU + seg0 * 4, Bl + bo);
        }
        {
            size_t ao = (size_t)(bm + r1l) * lda + k0 + seg1 * 8;
            cp_async16(pAh + r1l * SWU + seg1 * 4, Ah + ao);
            cp_async16(pAl + r1l * SWU + seg1 * 4, Al + ao);
            int rn = bn + r1l; if (rn > N - 1) rn = N - 1;
            size_t bo = (size_t)rn * ldb + k0 + seg1 * 8;
            cp_async16(pBh + r1l * SWU + seg1 * 4, Bh + bo);
            cp_async16(pBl + r1l * SWU + seg1 * 4, Bl + bo);
        }
    };

    float acc[2][8][4] = {};

    const int kbeg = kdiag ? bm : 0;
    const int ntile = (K - kbeg) / BK;

    load_stage(0, kbeg);
    cp_commit();

    for (int it = 0; it < ntile; it++) {
        const int s = it & 1;
        cp_wait<0>();
        __syncthreads();
        if (it + 1 < ntile) {
            load_stage(s ^ 1, kbeg + (it + 1) * BK);
            cp_commit();
        }

        const unsigned *pAh = bufs[s][0], *pAl = bufs[s][1];
        const unsigned *pBh = bufs[s][2], *pBl = bufs[s][3];

#pragma unroll
        for (int ks = 0; ks < 2; ks++) {
            const int kp = ks * 8 + tig;
            unsigned ah[2][4], al[2][4];
#pragma unroll
            for (int mt = 0; mt < 2; mt++) {
                int rr = wm + mt * 16 + g;
                ah[mt][0] = pAh[rr * SWU + kp];           ah[mt][1] = pAh[(rr + 8) * SWU + kp];
                ah[mt][2] = pAh[rr * SWU + kp + 4];       ah[mt][3] = pAh[(rr + 8) * SWU + kp + 4];
                al[mt][0] = pAl[rr * SWU + kp];           al[mt][1] = pAl[(rr + 8) * SWU + kp];
                al[mt][2] = pAl[rr * SWU + kp + 4];       al[mt][3] = pAl[(rr + 8) * SWU + kp + 4];
            }
#pragma unroll
            for (int nt = 0; nt < 8; nt++) {
                int c0 = wn + nt * 8 + g;
                unsigned bh0 = pBh[c0 * SWU + kp], bh1 = pBh[c0 * SWU + kp + 4];
                unsigned bl0 = pBl[c0 * SWU + kp], bl1 = pBl[c0 * SWU + kp + 4];
#pragma unroll
                for (int mt = 0; mt < 2; mt++) {
                    MMA_BF16(acc[mt][nt], ah[mt][0], ah[mt][1], ah[mt][2], ah[mt][3], bh0, bh1);
                    MMA_BF16(acc[mt][nt], al[mt][0], al[mt][1], al[mt][2], al[mt][3], bh0, bh1);
                    MMA_BF16(acc[mt][nt], ah[mt][0], ah[mt][1], ah[mt][2], ah[mt][3], bl0, bl1);
                }
            }
        }
        // no trailing sync: next iteration's cp_wait + __syncthreads protects
    }

    // Epilogue: fp32 and/or split bf16
#pragma unroll
    for (int mt = 0; mt < 2; mt++) {
        int row = bm + wm + mt * 16 + g;
#pragma unroll
        for (int nt = 0; nt < 8; nt++) {
            int col = bn + wn + nt * 8 + 2 * tig;
            if (col >= N) continue;
            size_t o0 = co + (size_t)row * ldc + col;
            size_t o1 = co + (size_t)(row + 8) * ldc + col;
            float v0 = alpha * acc[mt][nt][0], v1 = alpha * acc[mt][nt][1];
            float v2 = alpha * acc[mt][nt][2], v3 = alpha * acc[mt][nt][3];
            if (Cf) {
                *(float2*)(Cf + o0) = make_float2(v0, v1);
                *(float2*)(Cf + o1) = make_float2(v2, v3);
            }
            if (Ch) {
                bf16 h0, l0, h1, l1;
                splitf(v0, h0, l0); splitf(v1, h1, l1);
                *(__nv_bfloat162*)(Ch + o0) = __nv_bfloat162(h0, h1);
                *(__nv_bfloat162*)(Cl + o0) = __nv_bfloat162(l0, l1);
                splitf(v2, h0, l0); splitf(v3, h1, l1);
                *(__nv_bfloat162*)(Ch + o1) = __nv_bfloat162(h0, h1);
                *(__nv_bfloat162*)(Cl + o1) = __nv_bfloat162(l0, l1);
            }
        }
    }
}

// ------------------------------------------------------------------
// Elementwise split: fp32 -> (hi, lo)
// ------------------------------------------------------------------
__global__ void splitk(const float* __restrict__ in, bf16* __restrict__ hi,
                       bf16* __restrict__ lo, int n)
{
    int i = blockIdx.x * blockDim.x + threadIdx.x;
    if (i >= n) return;
    bf16 h, l;
    splitf(in[i], h, l);
    hi[i] = h; lo[i] = l;
}

// w: [E, NH, DC] -> out(h/l): [(n*E+e), c]
__global__ void repack_up_split(const float* __restrict__ w, bf16* __restrict__ oh,
                                bf16* __restrict__ ol, int E)
{
    int idx = blockIdx.x * blockDim.x + threadIdx.x;
    int total = E * NH * DC;
    if (idx >= total) return;
    int c = idx % DC;
    int rest = idx / DC;
    int n = rest % NH;
    int e = rest / NH;
    bf16 h, l;
    splitf(w[idx], h, l);
    size_t o = (size_t)(n * E + e) * DC + c;
    oh[o] = h; ol[o] = l;
}

// w_o: [D, DH, NH] -> Wt(h/l): [d, n*DH+e]
__global__ void repack_wo_split(const float* __restrict__ w)
{
    int idx = blockIdx.x * blockDim.x + threadIdx.x;
    int total = D * DH * NH;
    if (idx >= total) return;
    int n = idx % NH;
    int rest = idx / NH;
    int e = rest % DH;
    int d = rest / DH;
    bf16 h, l;
    splitf(w[idx], h, l);
    size_t o = (size_t)d * (NH * DH) + n * DH + e;
    g_Wth[o] = h; g_Wtl[o] = l;
}

// ------------------------------------------------------------------
// Assemble Q, K (split bf16) + V (fp32) per head + RoPE.  grid (T,NH), block 192
// ------------------------------------------------------------------
__global__ void assemble(const float* __restrict__ freqs)
{
    int t = blockIdx.x;
    int n = blockIdx.y;
    int i = threadIdx.x;
    size_t qo = ((size_t)n * T + t) * QKD + i;

    float qv, kv;
    if (i < DH) {
        qv = g_QC[(size_t)t * (NH * DH) + n * DH + i];
        kv = g_KC[(size_t)t * (NH * DH) + n * DH + i];
        g_v[((size_t)n * T + t) * DH + i] = g_VC[(size_t)t * (NH * DH) + n * DH + i];
    } else {
        int j = i - DH;
        int jr = j & 31;
        float ang = freqs[t * (DRH / 2) + jr];
        float cs, sn;
        sincosf(ang, &sn, &cs);
        float qre = g_QR[(size_t)t * (NH * DRH) + n * DRH + jr];
        float qim = g_QR[(size_t)t * (NH * DRH) + n * DRH + 32 + jr];
        float kre = g_kr[(size_t)t * DRH + jr];
        float kim = g_kr[(size_t)t * DRH + 32 + jr];
        if (j < 32) { qv = qre * cs - qim * sn; kv = (kre * cs - kim * sn) * (1.0f / NH); }
        else        { qv = qre * sn + qim * cs; kv = (kre * sn + kim * cs) * (1.0f / NH); }
    }
    bf16 h, l;
    splitf(qv, h, l); g_qh[qo] = h; g_ql[qo] = l;
    splitf(kv, h, l); g_kh[qo] = h; g_kl[qo] = l;
}

// ------------------------------------------------------------------
// Causal row softmax, in place on g_S. grid (T, NH), block 256.
// ------------------------------------------------------------------
__global__ void softmax_causal()
{
    int t = blockIdx.x;
    int n = blockIdx.y;
    float* row = g_S + ((size_t)n * T + t) * T;

    __shared__ float buf[T];
    __shared__ float red[256];
    int tid = threadIdx.x;
    int L = t + 1;

    float mx = -3.0e38f;
    for (int l = tid; l < L; l += 256) {
        float v = row[l];
        buf[l] = v;
        mx = fmaxf(mx, v);
    }
    red[tid] = mx;
    __syncthreads();
    for (int s = 128; s > 0; s >>= 1) {
        if (tid < s) red[tid] = fmaxf(red[tid], red[tid + s]);
        __syncthreads();
    }
    mx = red[0];
    __syncthreads();

    float sum = 0.0f;
    for (int l = tid; l < L; l += 256) {
        float e = __expf(buf[l] - mx);
        buf[l] = e;
        sum += e;
    }
    red[tid] = sum;
    __syncthreads();
    for (int s = 128; s > 0; s >>= 1) {
        if (tid < s) red[tid] += red[tid + s];
        __syncthreads();
    }
    float inv = 1.0f / red[0];
    for (int l = tid; l < T; l += 256) row[l] = (l < L) ? buf[l] * inv : 0.0f;
}

// ------------------------------------------------------------------
// 32x32 tiled transpose fp32 -> split bf16: out[c][r] = split(in[r][c]).
// block (32,8). grid (Cin/32, Rin/32, Z).
// tri=1: skip out-tiles never read by the diagonal-start PV GEMM.
// ------------------------------------------------------------------
__global__ void transpose32_split(const float* __restrict__ in,
                                  bf16* __restrict__ oh, bf16* __restrict__ ol,
                                  int Rin, int Cin, long long sIn, long long sOut, int tri)
{
    int cb = blockIdx.x;
    int rb = blockIdx.y;
    if (tri && rb < (cb & ~3)) return;
    const float* pin = in + (long long)blockIdx.z * sIn;
    bf16* phh = oh + (long long)blockIdx.z * sOut;
    bf16* pll = ol + (long long)blockIdx.z * sOut;

    __shared__ float tile[32][33];
    int tx = threadIdx.x, ty = threadIdx.y;
#pragma unroll
    for (int i = 0; i < 4; i++) {
        int r = rb * 32 + ty + i * 8;
        tile[ty + i * 8][tx] = pin[(size_t)r * Cin + cb * 32 + tx];
    }
    __syncthreads();
#pragma unroll
    for (int i = 0; i < 4; i++) {
        int c = cb * 32 + ty + i * 8;
        bf16 h, l;
        splitf(tile[tx][ty + i * 8], h, l);
        size_t o = (size_t)c * Rin + rb * 32 + tx;
        phh[o] = h; pll[o] = l;
    }
}

// ------------------------------------------------------------------
// Launch
// ------------------------------------------------------------------
static void* sym_addr(const void* symbol)
{
    void* p = nullptr;
    cudaGetSymbolAddress(&p, symbol);
    return p;
}

extern "C" void kernel_launch(void* const* d_in, const int* in_sizes, int n_in,
                              void* d_out, int out_size)
{
    const float* h     = (const float*)d_in[0];
    const float* freqs = (const float*)d_in[1];
    // d_in[2] = mask (unused: causal handled analytically)
    const float* w_dkv = (const float*)d_in[3];
    const float* w_uk  = (const float*)d_in[4];
    const float* w_uv  = (const float*)d_in[5];
    const float* w_dq  = (const float*)d_in[6];
    const float* w_uq  = (const float*)d_in[7];
    const float* w_qr  = (const float*)d_in[8];
    const float* w_kr  = (const float*)d_in[9];
    const float* w_o   = (const float*)d_in[10];
    float* out = (float*)d_out;

    cudaFuncSetAttribute(bgemm_nt, cudaFuncAttributeMaxDynamicSharedMemorySize, DYN_SMEM);

    bf16 *p_hh = (bf16*)sym_addr(g_hh), *p_hl = (bf16*)sym_addr(g_hl);
    bf16 *p_wdkvh = (bf16*)sym_addr(g_wdkvh), *p_wdkvl = (bf16*)sym_addr(g_wdkvl);
    bf16 *p_wdqh = (bf16*)sym_addr(g_wdqh), *p_wdql = (bf16*)sym_addr(g_wdql);
    bf16 *p_wkrh = (bf16*)sym_addr(g_wkrh), *p_wkrl = (bf16*)sym_addr(g_wkrl);
    bf16 *p_Bukh = (bf16*)sym_addr(g_Bukh), *p_Bukl = (bf16*)sym_addr(g_Bukl);
    bf16 *p_Buvh = (bf16*)sym_addr(g_Buvh), *p_Buvl = (bf16*)sym_addr(g_Buvl);
    bf16 *p_Buqh = (bf16*)sym_addr(g_Buqh), *p_Buql = (bf16*)sym_addr(g_Buql);
    bf16 *p_Bqrh = (bf16*)sym_addr(g_Bqrh), *p_Bqrl = (bf16*)sym_addr(g_Bqrl);
    bf16 *p_Wth = (bf16*)sym_addr(g_Wth), *p_Wtl = (bf16*)sym_addr(g_Wtl);
    bf16 *p_ckvh = (bf16*)sym_addr(g_ckvh), *p_ckvl = (bf16*)sym_addr(g_ckvl);
    bf16 *p_cqh = (bf16*)sym_addr(g_cqh), *p_cql = (bf16*)sym_addr(g_cql);
    float *p_kr = (float*)sym_addr(g_kr);
    float *p_KC = (float*)sym_addr(g_KC), *p_VC = (float*)sym_addr(g_VC);
    float *p_QC = (float*)sym_addr(g_QC), *p_QR = (float*)sym_addr(g_QR);
    bf16 *p_qh = (bf16*)sym_addr(g_qh), *p_ql = (bf16*)sym_addr(g_ql);
    bf16 *p_kh = (bf16*)sym_addr(g_kh), *p_kl = (bf16*)sym_addr(g_kl);
    float *p_v = (float*)sym_addr(g_v);
    bf16 *p_vth = (bf16*)sym_addr(g_vth), *p_vtl = (bf16*)sym_addr(g_vtl);
    float *p_S = (float*)sym_addr(g_S);
    bf16 *p_Sth = (bf16*)sym_addr(g_Sth), *p_Stl = (bf16*)sym_addr(g_Stl);
    bf16 *p_Uh = (bf16*)sym_addr(g_Uh), *p_Ul = (bf16*)sym_addr(g_Ul);

    const float scale = 1.0f / sqrtf((float)QKD);
    const int smem = DYN_SMEM;

    // 1) split inputs / repack weights into bf16 hi/lo
    splitk<<<(T * D + 255) / 256, 256>>>(h, p_hh, p_hl, T * D);
    splitk<<<(DC * D + 255) / 256, 256>>>(w_dkv, p_wdkvh, p_wdkvl, DC * D);
    splitk<<<(DC * D + 255) / 256, 256>>>(w_dq, p_wdqh, p_wdql, DC * D);
    splitk<<<(DRH * D + 255) / 256, 256>>>(w_kr, p_wkrh, p_wkrl, DRH * D);
    {
        int tot = DH * NH * DC;
        repack_up_split<<<(tot + 255) / 256, 256>>>(w_uk, p_Bukh, p_Bukl, DH);
        repack_up_split<<<(tot + 255) / 256, 256>>>(w_uv, p_Buvh, p_Buvl, DH);
        repack_up_split<<<(tot + 255) / 256, 256>>>(w_uq, p_Buqh, p_Buql, DH);
        int tot2 = DRH * NH * DC;
        repack_up_split<<<(tot2 + 255) / 256, 256>>>(w_qr, p_Bqrh, p_Bqrl, DRH);
        int tot3 = D * DH * NH;
        repack_wo_split<<<(tot3 + 255) / 256, 256>>>(w_o);
    }

    // 2) down projections (split outputs) + k_r (fp32 output)
    bgemm_nt<<<dim3(T / BM, DC / BN, 1), 256, smem>>>(p_hh, p_hl, p_wdkvh, p_wdkvl,
        nullptr, p_ckvh, p_ckvl, T, DC, D, D, D, DC, 1.0f, 0, 0, 0, 0, 0);
    bgemm_nt<<<dim3(T / BM, DC / BN, 1), 256, smem>>>(p_hh, p_hl, p_wdqh, p_wdql,
        nullptr, p_cqh, p_cql, T, DC, D, D, D, DC, 1.0f, 0, 0, 0, 0, 0);
    bgemm_nt<<<dim3(T / BM, 1, 1), 256, smem>>>(p_hh, p_hl, p_wkrh, p_wkrl,
        p_kr, nullptr, nullptr, T, DRH, D, D, D, DRH, 1.0f, 0, 0, 0, 0, 0);

    // 3) up projections (fp32 outputs -> assemble)
    bgemm_nt<<<dim3(T / BM, (NH * DH) / BN, 1), 256, smem>>>(p_ckvh, p_ckvl, p_Bukh, p_Bukl,
        p_KC, nullptr, nullptr, T, NH * DH, DC, DC, DC, NH * DH, 1.0f, 0, 0, 0, 0, 0);
    bgemm_nt<<<dim3(T / BM, (NH * DH) / BN, 1), 256, smem>>>(p_ckvh, p_ckvl, p_Buvh, p_Buvl,
        p_VC, nullptr, nullptr, T, NH * DH, DC, DC, DC, NH * DH, 1.0f, 0, 0, 0, 0, 0);
    bgemm_nt<<<dim3(T / BM, (NH * DH) / BN, 1), 256, smem>>>(p_cqh, p_cql, p_Buqh, p_Buql,
        p_QC, nullptr, nullptr, T, NH * DH, DC, DC, DC, NH * DH, 1.0f, 0, 0, 0, 0, 0);
    bgemm_nt<<<dim3(T / BM, (NH * DRH) / BN, 1), 256, smem>>>(p_cqh, p_cql, p_Bqrh, p_Bqrl,
        p_QR, nullptr, nullptr, T, NH * DRH, DC, DC, DC, NH * DRH, 1.0f, 0, 0, 0, 0, 0);

    // 4) assemble q/k (split) + v (fp32) with RoPE
    assemble<<<dim3(T, NH), QKD>>>(freqs);

    // 5) logits: S = scale * q @ k^T, causal tiles only, fp32 out
    bgemm_nt<<<dim3(T / BM, T / BN, NH), 256, smem>>>(p_qh, p_ql, p_kh, p_kl,
        p_S, nullptr, nullptr, T, T, QKD, QKD, QKD, T, scale,
        (long long)T * QKD, (long long)T * QKD, (long long)T * T, 1, 0);

    // 6) causal softmax (exact zeros above diagonal)
    softmax_causal<<<dim3(T, NH), 256>>>();

    // 7) transposes -> split bf16: S -> St(h/l) (pruned), v -> vt(h/l)
    transpose32_split<<<dim3(T / 32, T / 32, NH), dim3(32, 8)>>>(p_S, p_Sth, p_Stl, T, T,
        (long long)T * T, (long long)T * T, 1);
    transpose32_split<<<dim3(DH / 32, T / 32, NH), dim3(32, 8)>>>(p_v, p_vth, p_vtl, T, DH,
        (long long)T * DH, (long long)DH * T, 0);

    // 8) U = P^T @ V (split out), K-loop from diagonal
    bgemm_nt<<<dim3(T / BM, 1, NH), 256, smem>>>(p_Sth, p_Stl, p_vth, p_vtl,
        nullptr, p_Uh, p_Ul, T, DH, T, T, T, NH * DH, 1.0f,
        (long long)T * T, (long long)DH * T, (long long)DH, 0, 1);

    // 9) final: out = U @ Wt^T (fp32)
    bgemm_nt<<<dim3(T / BM, D / BN, 1), 256, smem>>>(p_Uh, p_Ul, p_Wth, p_Wtl,
        out, nullptr, nullptr, T, D, NH * DH, NH * DH, D, D, 1.0f, 0, 0, 0, 0, 0);
}